// round 1
// baseline (speedup 1.0000x reference)
#include <cuda_runtime.h>
#include <math.h>

#define DIMC   128
#define HEADS  8
#define HD     16
#define DD     5
#define HH     24
#define WW     48
#define NP     (DD*HH*WW)   /* 5760 positions */
#define NNB    245          /* 5*7*7 neighbors */

// Scratch (no cudaMalloc allowed): qkv = 5760*384 floats (8.85MB), att = 5760*128 (2.95MB)
__device__ float g_qkv[NP * 3 * DIMC];
__device__ float g_att[NP * DIMC];

// ---------------------------------------------------------------------------
// Generic GEMM: C[M][N] = A[M][128] @ B[N][128]^T + bias[N]
// BM=BN=64, BK=32, 256 threads, 4x4 micro-tile per thread.
// M and N must be multiples of 64 (5760, 384, 128 all are).
// ---------------------------------------------------------------------------
__global__ void gemm_k128(const float* __restrict__ A, const float* __restrict__ B,
                          const float* __restrict__ bias, float* __restrict__ C,
                          int N)
{
    __shared__ float As[64][36];
    __shared__ float Bs[64][36];
    const int bm = blockIdx.x * 64;
    const int bn = blockIdx.y * 64;
    const int tid = threadIdx.x;
    const int tx = tid & 15, ty = tid >> 4;

    float acc[4][4] = {};

    for (int k0 = 0; k0 < 128; k0 += 32) {
        // Load 64x32 tiles (512 float4 each) with 256 threads -> 2 float4/thread/matrix
#pragma unroll
        for (int t = 0; t < 2; t++) {
            int i  = tid + t * 256;       // 0..511
            int r  = i >> 3;              // row 0..63
            int c4 = i & 7;               // float4 index within 32-col tile
            float4 va = *(const float4*)(A + (size_t)(bm + r) * 128 + k0 + c4 * 4);
            *(float4*)(&As[r][c4 * 4]) = va;
            float4 vb = *(const float4*)(B + (size_t)(bn + r) * 128 + k0 + c4 * 4);
            *(float4*)(&Bs[r][c4 * 4]) = vb;
        }
        __syncthreads();

#pragma unroll
        for (int kk = 0; kk < 32; kk++) {
            float a[4], b[4];
#pragma unroll
            for (int i = 0; i < 4; i++) a[i] = As[ty + 16 * i][kk];
#pragma unroll
            for (int j = 0; j < 4; j++) b[j] = Bs[tx + 16 * j][kk];
#pragma unroll
            for (int i = 0; i < 4; i++)
#pragma unroll
                for (int j = 0; j < 4; j++)
                    acc[i][j] += a[i] * b[j];
        }
        __syncthreads();
    }

#pragma unroll
    for (int i = 0; i < 4; i++) {
        int row = bm + ty + 16 * i;
#pragma unroll
        for (int j = 0; j < 4; j++) {
            int col = bn + tx + 16 * j;
            C[(size_t)row * N + col] = acc[i][j] + bias[col];
        }
    }
}

// ---------------------------------------------------------------------------
// Neighborhood attention: one block per position, 8 warps = 8 heads.
// Within a warp: 8 groups of 4 lanes; group handles one neighbor at a time,
// each lane loads a float4 (4 dims) of the 16-dim head row -> 64B coalesced.
// Two-pass softmax over 245 neighbors with scores staged in smem.
// ---------------------------------------------------------------------------
__global__ void attn_kernel(const float* __restrict__ qkv, float* __restrict__ out)
{
    const int p  = blockIdx.x;
    const int d  = p / (HH * WW);
    const int hw = p % (HH * WW);
    const int hy = hw / WW;
    const int wx = hw % WW;

    const int warp = threadIdx.x >> 5;   // head
    const int lane = threadIdx.x & 31;
    const int grp  = lane >> 2;          // 0..7
    const int sub  = lane & 3;           // 0..3

    __shared__ float q_s[DIMC];
    __shared__ float sc[HEADS][NNB + 3];
    __shared__ int   nidx[NNB];

    // Load center query row (128 floats)
    if (threadIdx.x < 32) {
        float4 v = *(const float4*)(qkv + (size_t)p * 384 + threadIdx.x * 4);
        *(float4*)(&q_s[threadIdx.x * 4]) = v;
    }
    // Precompute circular neighbor flat indices
    for (int n = threadIdx.x; n < NNB; n += blockDim.x) {
        int od = n / 49;
        int rm = n % 49;
        int oh = rm / 7;
        int ow = rm % 7;
        int dd = d + od - 2;  dd += (dd < 0) ? DD : 0;  dd -= (dd >= DD) ? DD : 0;
        int h2 = hy + oh - 3; h2 += (h2 < 0) ? HH : 0;  h2 -= (h2 >= HH) ? HH : 0;
        int w2 = wx + ow - 3; w2 += (w2 < 0) ? WW : 0;  w2 -= (w2 >= WW) ? WW : 0;
        nidx[n] = (dd * HH + h2) * WW + w2;
    }
    __syncthreads();

    const float4 qf = *(const float4*)(&q_s[warp * HD + sub * 4]);
    const float scale = 0.25f;  // hd^-0.5 = 16^-0.5

    // ---- Pass 1: scores + running max ----
    float m = -1e30f;
#pragma unroll 4
    for (int i = 0; i < 31; i++) {
        int n = i * 8 + grp;
        bool valid = (n < NNB);
        int np = valid ? nidx[n] : nidx[0];
        const float4 kf = *(const float4*)(qkv + (size_t)np * 384 + 128 + warp * HD + sub * 4);
        float dot = qf.x * kf.x + qf.y * kf.y + qf.z * kf.z + qf.w * kf.w;
        dot += __shfl_xor_sync(0xFFFFFFFF, dot, 1);
        dot += __shfl_xor_sync(0xFFFFFFFF, dot, 2);
        float s = dot * scale;
        if (valid) {
            if (sub == 0) sc[warp][n] = s;
            m = fmaxf(m, s);
        }
    }
#pragma unroll
    for (int o = 16; o >= 1; o >>= 1)
        m = fmaxf(m, __shfl_xor_sync(0xFFFFFFFF, m, o));
    __syncwarp();

    // ---- Pass 2: exponentiate + sum ----
    float sum = 0.0f;
#pragma unroll
    for (int n = lane; n < NNB; n += 32) {
        float e = __expf(sc[warp][n] - m);
        sc[warp][n] = e;
        sum += e;
    }
#pragma unroll
    for (int o = 16; o >= 1; o >>= 1)
        sum += __shfl_xor_sync(0xFFFFFFFF, sum, o);
    const float inv = 1.0f / sum;
    __syncwarp();

    // ---- Pass 3: weighted V accumulation ----
    float4 acc = make_float4(0.f, 0.f, 0.f, 0.f);
#pragma unroll 4
    for (int i = 0; i < 31; i++) {
        int n = i * 8 + grp;
        if (n < NNB) {
            int np = nidx[n];
            const float4 vf = *(const float4*)(qkv + (size_t)np * 384 + 256 + warp * HD + sub * 4);
            float w = sc[warp][n];
            acc.x += w * vf.x; acc.y += w * vf.y;
            acc.z += w * vf.z; acc.w += w * vf.w;
        }
    }
    // Reduce across the 8 groups (lanes sharing `sub`)
#pragma unroll
    for (int o = 4; o <= 16; o <<= 1) {
        acc.x += __shfl_xor_sync(0xFFFFFFFF, acc.x, o);
        acc.y += __shfl_xor_sync(0xFFFFFFFF, acc.y, o);
        acc.z += __shfl_xor_sync(0xFFFFFFFF, acc.z, o);
        acc.w += __shfl_xor_sync(0xFFFFFFFF, acc.w, o);
    }
    if (grp == 0) {
        acc.x *= inv; acc.y *= inv; acc.z *= inv; acc.w *= inv;
        *(float4*)(out + (size_t)p * DIMC + warp * HD + sub * 4) = acc;
    }
}

// ---------------------------------------------------------------------------
extern "C" void kernel_launch(void* const* d_in, const int* in_sizes, int n_in,
                              void* d_out, int out_size)
{
    const float* x      = (const float*)d_in[0];
    const float* qkv_w  = (const float*)d_in[1];
    const float* qkv_b  = (const float*)d_in[2];
    const float* proj_w = (const float*)d_in[3];
    const float* proj_b = (const float*)d_in[4];
    float* out = (float*)d_out;

    float *qkv, *att;
    cudaGetSymbolAddress((void**)&qkv, g_qkv);
    cudaGetSymbolAddress((void**)&att, g_att);

    // QKV projection: (5760,128) @ (384,128)^T + b
    gemm_k128<<<dim3(NP / 64, 384 / 64), 256>>>(x, qkv_w, qkv_b, qkv, 384);
    // Neighborhood attention
    attn_kernel<<<NP, 256>>>(qkv, att);
    // Output projection: (5760,128) @ (128,128)^T + b
    gemm_k128<<<dim3(NP / 64, 128 / 64), 256>>>(att, proj_w, proj_b, out, 128);
}

// round 3
// speedup vs baseline: 1.2092x; 1.2092x over previous
#include <cuda_runtime.h>
#include <cuda_fp16.h>
#include <math.h>

#define DIMC   128
#define HEADS  8
#define HD     16
#define DD     5
#define HH     24
#define WWID   48
#define NP     (DD*HH*WWID)   /* 5760 */
#define NH     576            /* padded halo rows (560 real) */
#define NREAL  560
#define RS     24             /* smem row stride in halves (48B, conflict-free for ldmatrix) */

typedef unsigned int u32;

// Scratch
__device__ __half g_qh[NP * DIMC];
__device__ __half g_kh[NP * DIMC];
__device__ __half g_vh[NP * DIMC];
__device__ float  g_att[NP * DIMC];

// ---------------------------------------------------------------------------
// fp32 GEMM C = A @ B^T + bias  (K=128), 64x64 tile
// ---------------------------------------------------------------------------
__global__ void gemm_k128(const float* __restrict__ A, const float* __restrict__ B,
                          const float* __restrict__ bias, float* __restrict__ C, int N)
{
    __shared__ float As[64][36];
    __shared__ float Bs[64][36];
    const int bm = blockIdx.x * 64, bn = blockIdx.y * 64;
    const int tid = threadIdx.x;
    const int tx = tid & 15, ty = tid >> 4;
    float acc[4][4] = {};
    for (int k0 = 0; k0 < 128; k0 += 32) {
#pragma unroll
        for (int t = 0; t < 2; t++) {
            int i = tid + t * 256, r = i >> 3, c4 = i & 7;
            *(float4*)(&As[r][c4 * 4]) = *(const float4*)(A + (size_t)(bm + r) * 128 + k0 + c4 * 4);
            *(float4*)(&Bs[r][c4 * 4]) = *(const float4*)(B + (size_t)(bn + r) * 128 + k0 + c4 * 4);
        }
        __syncthreads();
#pragma unroll
        for (int kk = 0; kk < 32; kk++) {
            float a[4], b[4];
#pragma unroll
            for (int i = 0; i < 4; i++) a[i] = As[ty + 16 * i][kk];
#pragma unroll
            for (int j = 0; j < 4; j++) b[j] = Bs[tx + 16 * j][kk];
#pragma unroll
            for (int i = 0; i < 4; i++)
#pragma unroll
                for (int j = 0; j < 4; j++) acc[i][j] += a[i] * b[j];
        }
        __syncthreads();
    }
#pragma unroll
    for (int i = 0; i < 4; i++) {
        int row = bm + ty + 16 * i;
#pragma unroll
        for (int j = 0; j < 4; j++) {
            int col = bn + tx + 16 * j;
            C[(size_t)row * N + col] = acc[i][j] + bias[col];
        }
    }
}

// Same GEMM but epilogue writes fp16 q(*0.25)/k/v  (N=384 fixed)
__global__ void gemm_qkv_h(const float* __restrict__ A, const float* __restrict__ B,
                           const float* __restrict__ bias)
{
    __shared__ float As[64][36];
    __shared__ float Bs[64][36];
    const int bm = blockIdx.x * 64, bn = blockIdx.y * 64;
    const int tid = threadIdx.x;
    const int tx = tid & 15, ty = tid >> 4;
    float acc[4][4] = {};
    for (int k0 = 0; k0 < 128; k0 += 32) {
#pragma unroll
        for (int t = 0; t < 2; t++) {
            int i = tid + t * 256, r = i >> 3, c4 = i & 7;
            *(float4*)(&As[r][c4 * 4]) = *(const float4*)(A + (size_t)(bm + r) * 128 + k0 + c4 * 4);
            *(float4*)(&Bs[r][c4 * 4]) = *(const float4*)(B + (size_t)(bn + r) * 128 + k0 + c4 * 4);
        }
        __syncthreads();
#pragma unroll
        for (int kk = 0; kk < 32; kk++) {
            float a[4], b[4];
#pragma unroll
            for (int i = 0; i < 4; i++) a[i] = As[ty + 16 * i][kk];
#pragma unroll
            for (int j = 0; j < 4; j++) b[j] = Bs[tx + 16 * j][kk];
#pragma unroll
            for (int i = 0; i < 4; i++)
#pragma unroll
                for (int j = 0; j < 4; j++) acc[i][j] += a[i] * b[j];
        }
        __syncthreads();
    }
#pragma unroll
    for (int i = 0; i < 4; i++) {
        int row = bm + ty + 16 * i;
#pragma unroll
        for (int j = 0; j < 4; j++) {
            int col = bn + tx + 16 * j;
            float val = acc[i][j] + bias[col];
            if (col < 128)       g_qh[(size_t)row * 128 + col]       = __float2half(val * 0.25f);
            else if (col < 256)  g_kh[(size_t)row * 128 + col - 128] = __float2half(val);
            else                 g_vh[(size_t)row * 128 + col - 256] = __float2half(val);
        }
    }
}

// ---------------------------------------------------------------------------
// mma helpers
// ---------------------------------------------------------------------------
__device__ __forceinline__ u32 smaddr(const void* p) { return (u32)__cvta_generic_to_shared(p); }

__device__ __forceinline__ void ldsm_x4(u32& r0, u32& r1, u32& r2, u32& r3, u32 a) {
    asm volatile("ldmatrix.sync.aligned.m8n8.x4.shared.b16 {%0,%1,%2,%3},[%4];"
                 : "=r"(r0), "=r"(r1), "=r"(r2), "=r"(r3) : "r"(a));
}
__device__ __forceinline__ void ldsm_x2(u32& r0, u32& r1, u32 a) {
    asm volatile("ldmatrix.sync.aligned.m8n8.x2.shared.b16 {%0,%1},[%2];"
                 : "=r"(r0), "=r"(r1) : "r"(a));
}
__device__ __forceinline__ void ldsm_x4_t(u32& r0, u32& r1, u32& r2, u32& r3, u32 a) {
    asm volatile("ldmatrix.sync.aligned.m8n8.x4.trans.shared.b16 {%0,%1,%2,%3},[%4];"
                 : "=r"(r0), "=r"(r1), "=r"(r2), "=r"(r3) : "r"(a));
}
__device__ __forceinline__ void ldsm_x2_t(u32& r0, u32& r1, u32 a) {
    asm volatile("ldmatrix.sync.aligned.m8n8.x2.trans.shared.b16 {%0,%1},[%2];"
                 : "=r"(r0), "=r"(r1) : "r"(a));
}
__device__ __forceinline__ void mma16816(float* d, u32 a0, u32 a1, u32 a2, u32 a3, u32 b0, u32 b1) {
    asm volatile("mma.sync.aligned.m16n8k16.row.col.f32.f16.f16.f32 "
                 "{%0,%1,%2,%3},{%4,%5,%6,%7},{%8,%9},{%0,%1,%2,%3};"
                 : "+f"(d[0]), "+f"(d[1]), "+f"(d[2]), "+f"(d[3])
                 : "r"(a0), "r"(a1), "r"(a2), "r"(a3), "r"(b0), "r"(b1));
}
__device__ __forceinline__ void mma1688(float* d, u32 a0, u32 a1, u32 b0) {
    asm volatile("mma.sync.aligned.m16n8k8.row.col.f32.f16.f16.f32 "
                 "{%0,%1,%2,%3},{%4,%5},{%6},{%0,%1,%2,%3};"
                 : "+f"(d[0]), "+f"(d[1]), "+f"(d[2]), "+f"(d[3])
                 : "r"(a0), "r"(a1), "r"(b0));
}
__device__ __forceinline__ u32 packh2(float x, float y) {
    __half2 h = __floats2half2_rn(x, y);
    return *(u32*)&h;
}

struct SmemAttn {
    __half K[NH * RS];
    __half V[NH * RS];
    __half Q[16 * RS];
    float  red1[8][16];
    float  red2[8][16];
    float  invr[16];
    float  os[8][16][16];
    int    gh[8];
    int    gw[14];
    unsigned char colcode[NH];
};

// ---------------------------------------------------------------------------
// Tiled neighborhood attention: block = (2x8 position tile) x (1 head).
// Masked-dense S[16 x 576] = Q*K^T on tensor cores, softmax, O = P*V.
// 8 warps split the 576 halo columns (72 each).
// ---------------------------------------------------------------------------
__global__ __launch_bounds__(256) void attn_mma(void)
{
    extern __shared__ char smraw[];
    SmemAttn* sm = (SmemAttn*)smraw;

    const int tid  = threadIdx.x;
    const int warp = tid >> 5;
    const int lane = tid & 31;

    const int head = blockIdx.x & 7;
    const int tile = blockIdx.x >> 3;
    const int tw   = tile % 6;
    const int th   = (tile / 6) % 12;
    const int d0   = tile / 72;
    const int hy0  = th * 2;
    const int wx0  = tw * 8;

    // ---- phase 0: tables + Q ----
    if (tid < 8)                 sm->gh[tid]       = (hy0 + tid + 21) % HH;
    if (tid >= 32 && tid < 46)   sm->gw[tid - 32]  = (wx0 + tid - 32 + 45) % WWID;
    for (int c = tid; c < NH; c += 256) {
        unsigned char code = 0xFF;
        if (c < NREAL) { int rem = c % 112; code = (unsigned char)(((rem / 14) << 4) | (rem % 14)); }
        sm->colcode[c] = code;
    }
    {   // Q tile: 16 pos x 16 dims
        int r = tid >> 4, k = tid & 15;
        int gp = ((d0 * HH + hy0 + (r >> 3)) * WWID + wx0 + (r & 7));
        sm->Q[r * RS + k] = g_qh[(size_t)gp * DIMC + head * HD + k];
    }
    __syncthreads();

    // ---- phase 1: halo K/V load (fp16) ----
    {
        const __half2 zz = __floats2half2_rn(0.f, 0.f);
        __half2* Kp = (__half2*)sm->K;
        __half2* Vp = (__half2*)sm->V;
        for (int e = tid; e < NH * 16; e += 256) {
            int row = e >> 4;
            int q   = e & 15;
            int isv = q >> 3;
            int k2  = q & 7;
            __half2 val = zz;
            if (row < NREAL) {
                int d   = row / 112;
                int rem = row % 112;
                int g   = (d * HH + sm->gh[rem / 14]) * WWID + sm->gw[rem % 14];
                const __half* src = (isv ? g_vh : g_kh) + (size_t)g * DIMC + head * HD + k2 * 2;
                val = *(const __half2*)src;
            }
            (isv ? Vp : Kp)[row * (RS / 2) + k2] = val;
        }
    }
    __syncthreads();

    // ---- scores: S[16 x 72] per warp ----
    const u32 qb = smaddr(sm->Q);
    const u32 kb = smaddr(sm->K);
    const u32 vb = smaddr(sm->V);
    const int nb = warp * 72;

    u32 qa0, qa1, qa2, qa3;
    {
        int l4 = lane & 15, cg = lane >> 4;
        ldsm_x4(qa0, qa1, qa2, qa3, qb + (u32)(l4 * RS + cg * 8) * 2);
    }

    float c[9][4];
#pragma unroll
    for (int t = 0; t < 9; t++) { c[t][0] = c[t][1] = c[t][2] = c[t][3] = 0.f; }

#pragma unroll
    for (int t = 0; t < 9; t++) {
        int l4 = lane & 15;
        u32 addr = kb + (u32)((nb + t * 8 + (l4 & 7)) * RS + (l4 >> 3) * 8) * 2;
        u32 b0, b1;
        ldsm_x2(b0, b1, addr);
        mma16816(c[t], qa0, qa1, qa2, qa3, b0, b1);
    }

    // ---- mask + row max ----
    const int r0 = lane >> 2;         // tile row i=0, j=r0
    const int r1 = r0 + 8;            // tile row i=1, same j
    const int j  = r0;
    float mx0 = -1e30f, mx1 = -1e30f;
#pragma unroll
    for (int t = 0; t < 9; t++) {
        int cA = nb + t * 8 + 2 * (lane & 3);
        unsigned codeA = sm->colcode[cA];
        unsigned codeB = sm->colcode[cA + 1];
        int hA = codeA >> 4, wA = codeA & 15;
        int hB = codeB >> 4, wB = codeB & 15;
        bool vwA = (wA >= j) && (wA <= j + 6);
        bool vwB = (wB >= j) && (wB <= j + 6);
        if (!(vwA && hA <= 6)) c[t][0] = -1e30f;
        if (!(vwB && hB <= 6)) c[t][1] = -1e30f;
        if (!(vwA && hA >= 1)) c[t][2] = -1e30f;
        if (!(vwB && hB >= 1)) c[t][3] = -1e30f;
        mx0 = fmaxf(mx0, fmaxf(c[t][0], c[t][1]));
        mx1 = fmaxf(mx1, fmaxf(c[t][2], c[t][3]));
    }
    mx0 = fmaxf(mx0, __shfl_xor_sync(0xFFFFFFFF, mx0, 1));
    mx0 = fmaxf(mx0, __shfl_xor_sync(0xFFFFFFFF, mx0, 2));
    mx1 = fmaxf(mx1, __shfl_xor_sync(0xFFFFFFFF, mx1, 1));
    mx1 = fmaxf(mx1, __shfl_xor_sync(0xFFFFFFFF, mx1, 2));
    if ((lane & 3) == 0) { sm->red1[warp][r0] = mx0; sm->red1[warp][r1] = mx1; }
    __syncthreads();

    float M0 = sm->red1[0][r0], M1 = sm->red1[0][r1];
#pragma unroll
    for (int w = 1; w < 8; w++) {
        M0 = fmaxf(M0, sm->red1[w][r0]);
        M1 = fmaxf(M1, sm->red1[w][r1]);
    }

    // ---- exp + row sum ----
    float s0 = 0.f, s1 = 0.f;
#pragma unroll
    for (int t = 0; t < 9; t++) {
        c[t][0] = __expf(c[t][0] - M0); s0 += c[t][0];
        c[t][1] = __expf(c[t][1] - M0); s0 += c[t][1];
        c[t][2] = __expf(c[t][2] - M1); s1 += c[t][2];
        c[t][3] = __expf(c[t][3] - M1); s1 += c[t][3];
    }
    s0 += __shfl_xor_sync(0xFFFFFFFF, s0, 1);
    s0 += __shfl_xor_sync(0xFFFFFFFF, s0, 2);
    s1 += __shfl_xor_sync(0xFFFFFFFF, s1, 1);
    s1 += __shfl_xor_sync(0xFFFFFFFF, s1, 2);
    if ((lane & 3) == 0) { sm->red2[warp][r0] = s0; sm->red2[warp][r1] = s1; }
    __syncthreads();

    if (warp == 0 && (lane & 3) == 0) {
        float S0 = 0.f, S1 = 0.f;
#pragma unroll
        for (int w = 0; w < 8; w++) { S0 += sm->red2[w][r0]; S1 += sm->red2[w][r1]; }
        sm->invr[r0] = 1.f / S0;
        sm->invr[r1] = 1.f / S1;
    }

    // ---- O_partial = P @ V  (per-warp over its 72 cols) ----
    float dacc[8];
#pragma unroll
    for (int i = 0; i < 8; i++) dacc[i] = 0.f;

#pragma unroll
    for (int kc = 0; kc < 4; kc++) {
        u32 a0 = packh2(c[2 * kc][0], c[2 * kc][1]);
        u32 a1 = packh2(c[2 * kc][2], c[2 * kc][3]);
        u32 a2 = packh2(c[2 * kc + 1][0], c[2 * kc + 1][1]);
        u32 a3 = packh2(c[2 * kc + 1][2], c[2 * kc + 1][3]);
        int g = lane >> 3, rr = lane & 7;
        int row = nb + kc * 16 + ((g & 1) << 3) + rr;
        u32 addr = vb + (u32)(row * RS + (g >> 1) * 8) * 2;
        u32 b0, b1, b2, b3;
        ldsm_x4_t(b0, b1, b2, b3, addr);
        mma16816(dacc,     qa0 = a0, a1, a2, a3, b0, b1);   // note: qa0 reuse avoided below
        mma16816(dacc + 4, a0, a1, a2, a3, b2, b3);
    }
    {   // tail: k=8 (cols 64..71)
        u32 a0 = packh2(c[8][0], c[8][1]);
        u32 a1 = packh2(c[8][2], c[8][3]);
        int l4 = lane & 15;
        int row = nb + 64 + (l4 & 7);
        u32 addr = vb + (u32)(row * RS + (l4 >> 3) * 8) * 2;
        u32 b0, b1;
        ldsm_x2_t(b0, b1, addr);
        mma1688(dacc,     a0, a1, b0);
        mma1688(dacc + 4, a0, a1, b1);
    }

    // ---- stage partial outputs, reduce across warps ----
    {
        int q4 = lane & 3;
        sm->os[warp][r0][2 * q4 + 0] = dacc[0];
        sm->os[warp][r0][2 * q4 + 1] = dacc[1];
        sm->os[warp][r1][2 * q4 + 0] = dacc[2];
        sm->os[warp][r1][2 * q4 + 1] = dacc[3];
        sm->os[warp][r0][8 + 2 * q4 + 0] = dacc[4];
        sm->os[warp][r0][8 + 2 * q4 + 1] = dacc[5];
        sm->os[warp][r1][8 + 2 * q4 + 0] = dacc[6];
        sm->os[warp][r1][8 + 2 * q4 + 1] = dacc[7];
    }
    __syncthreads();

    {
        int r = tid >> 4, k = tid & 15;
        float s = 0.f;
#pragma unroll
        for (int w = 0; w < 8; w++) s += sm->os[w][r][k];
        s *= sm->invr[r];
        int gp = ((d0 * HH + hy0 + (r >> 3)) * WWID + wx0 + (r & 7));
        g_att[(size_t)gp * DIMC + head * HD + k] = s;
    }
}

// ---------------------------------------------------------------------------
extern "C" void kernel_launch(void* const* d_in, const int* in_sizes, int n_in,
                              void* d_out, int out_size)
{
    const float* x      = (const float*)d_in[0];
    const float* qkv_w  = (const float*)d_in[1];
    const float* qkv_b  = (const float*)d_in[2];
    const float* proj_w = (const float*)d_in[3];
    const float* proj_b = (const float*)d_in[4];
    float* out = (float*)d_out;

    float* att;
    cudaGetSymbolAddress((void**)&att, g_att);

    static int smem_set = 0;
    if (!smem_set) {
        cudaFuncSetAttribute(attn_mma, cudaFuncAttributeMaxDynamicSharedMemorySize,
                             (int)sizeof(SmemAttn));
        smem_set = 1;
    }

    // QKV projection -> fp16 q(*0.25)/k/v
    gemm_qkv_h<<<dim3(NP / 64, 384 / 64), 256>>>(x, qkv_w, qkv_b);
    // Tiled tensor-core neighborhood attention
    attn_mma<<<(NP / 16) * HEADS, 256, sizeof(SmemAttn)>>>();
    // Output projection
    gemm_k128<<<dim3(NP / 64, 128 / 64), 256>>>(att, proj_w, proj_b, out, 128);
}

// round 4
// speedup vs baseline: 1.8153x; 1.5012x over previous
#include <cuda_runtime.h>
#include <cuda_fp16.h>
#include <math.h>

#define DIMC   128
#define HEADS  8
#define HD     16
#define DD     5
#define HH     24
#define WWID   48
#define NP     (DD*HH*WWID)   /* 5760 */
#define NH     576            /* padded halo rows (560 real) */
#define NREAL  560
#define RS     24             /* smem row stride in halves (48B) */

typedef unsigned int u32;

// Scratch
__device__ __half g_qh[NP * DIMC];
__device__ __half g_kh[NP * DIMC];
__device__ __half g_vh[NP * DIMC];
__device__ float  g_att[NP * DIMC];

// ---------------------------------------------------------------------------
// fp32 GEMM C = A @ B^T + bias  (K=128), 64x64 tile
// ---------------------------------------------------------------------------
__global__ void gemm_k128(const float* __restrict__ A, const float* __restrict__ B,
                          const float* __restrict__ bias, float* __restrict__ C, int N)
{
    __shared__ float As[64][36];
    __shared__ float Bs[64][36];
    const int bm = blockIdx.x * 64, bn = blockIdx.y * 64;
    const int tid = threadIdx.x;
    const int tx = tid & 15, ty = tid >> 4;
    float acc[4][4] = {};
    for (int k0 = 0; k0 < 128; k0 += 32) {
#pragma unroll
        for (int t = 0; t < 2; t++) {
            int i = tid + t * 256, r = i >> 3, c4 = i & 7;
            *(float4*)(&As[r][c4 * 4]) = *(const float4*)(A + (size_t)(bm + r) * 128 + k0 + c4 * 4);
            *(float4*)(&Bs[r][c4 * 4]) = *(const float4*)(B + (size_t)(bn + r) * 128 + k0 + c4 * 4);
        }
        __syncthreads();
#pragma unroll
        for (int kk = 0; kk < 32; kk++) {
            float a[4], b[4];
#pragma unroll
            for (int i = 0; i < 4; i++) a[i] = As[ty + 16 * i][kk];
#pragma unroll
            for (int j = 0; j < 4; j++) b[j] = Bs[tx + 16 * j][kk];
#pragma unroll
            for (int i = 0; i < 4; i++)
#pragma unroll
                for (int j = 0; j < 4; j++) acc[i][j] += a[i] * b[j];
        }
        __syncthreads();
    }
#pragma unroll
    for (int i = 0; i < 4; i++) {
        int row = bm + ty + 16 * i;
#pragma unroll
        for (int j = 0; j < 4; j++) {
            int col = bn + tx + 16 * j;
            C[(size_t)row * N + col] = acc[i][j] + bias[col];
        }
    }
}

// Same GEMM but epilogue writes fp16 q(*0.25)/k/v  (N=384 fixed)
__global__ void gemm_qkv_h(const float* __restrict__ A, const float* __restrict__ B,
                           const float* __restrict__ bias)
{
    __shared__ float As[64][36];
    __shared__ float Bs[64][36];
    const int bm = blockIdx.x * 64, bn = blockIdx.y * 64;
    const int tid = threadIdx.x;
    const int tx = tid & 15, ty = tid >> 4;
    float acc[4][4] = {};
    for (int k0 = 0; k0 < 128; k0 += 32) {
#pragma unroll
        for (int t = 0; t < 2; t++) {
            int i = tid + t * 256, r = i >> 3, c4 = i & 7;
            *(float4*)(&As[r][c4 * 4]) = *(const float4*)(A + (size_t)(bm + r) * 128 + k0 + c4 * 4);
            *(float4*)(&Bs[r][c4 * 4]) = *(const float4*)(B + (size_t)(bn + r) * 128 + k0 + c4 * 4);
        }
        __syncthreads();
#pragma unroll
        for (int kk = 0; kk < 32; kk++) {
            float a[4], b[4];
#pragma unroll
            for (int i = 0; i < 4; i++) a[i] = As[ty + 16 * i][kk];
#pragma unroll
            for (int j = 0; j < 4; j++) b[j] = Bs[tx + 16 * j][kk];
#pragma unroll
            for (int i = 0; i < 4; i++)
#pragma unroll
                for (int j = 0; j < 4; j++) acc[i][j] += a[i] * b[j];
        }
        __syncthreads();
    }
#pragma unroll
    for (int i = 0; i < 4; i++) {
        int row = bm + ty + 16 * i;
#pragma unroll
        for (int j = 0; j < 4; j++) {
            int col = bn + tx + 16 * j;
            float val = acc[i][j] + bias[col];
            if (col < 128)       g_qh[(size_t)row * 128 + col]       = __float2half(val * 0.25f);
            else if (col < 256)  g_kh[(size_t)row * 128 + col - 128] = __float2half(val);
            else                 g_vh[(size_t)row * 128 + col - 256] = __float2half(val);
        }
    }
}

// ---------------------------------------------------------------------------
// mma helpers
// ---------------------------------------------------------------------------
__device__ __forceinline__ u32 smaddr(const void* p) { return (u32)__cvta_generic_to_shared(p); }

__device__ __forceinline__ void ldsm_x4(u32& r0, u32& r1, u32& r2, u32& r3, u32 a) {
    asm volatile("ldmatrix.sync.aligned.m8n8.x4.shared.b16 {%0,%1,%2,%3},[%4];"
                 : "=r"(r0), "=r"(r1), "=r"(r2), "=r"(r3) : "r"(a));
}
__device__ __forceinline__ void ldsm_x2(u32& r0, u32& r1, u32 a) {
    asm volatile("ldmatrix.sync.aligned.m8n8.x2.shared.b16 {%0,%1},[%2];"
                 : "=r"(r0), "=r"(r1) : "r"(a));
}
__device__ __forceinline__ void ldsm_x4_t(u32& r0, u32& r1, u32& r2, u32& r3, u32 a) {
    asm volatile("ldmatrix.sync.aligned.m8n8.x4.trans.shared.b16 {%0,%1,%2,%3},[%4];"
                 : "=r"(r0), "=r"(r1), "=r"(r2), "=r"(r3) : "r"(a));
}
__device__ __forceinline__ void ldsm_x2_t(u32& r0, u32& r1, u32 a) {
    asm volatile("ldmatrix.sync.aligned.m8n8.x2.trans.shared.b16 {%0,%1},[%2];"
                 : "=r"(r0), "=r"(r1) : "r"(a));
}
__device__ __forceinline__ void mma16816(float* d, u32 a0, u32 a1, u32 a2, u32 a3, u32 b0, u32 b1) {
    asm volatile("mma.sync.aligned.m16n8k16.row.col.f32.f16.f16.f32 "
                 "{%0,%1,%2,%3},{%4,%5,%6,%7},{%8,%9},{%0,%1,%2,%3};"
                 : "+f"(d[0]), "+f"(d[1]), "+f"(d[2]), "+f"(d[3])
                 : "r"(a0), "r"(a1), "r"(a2), "r"(a3), "r"(b0), "r"(b1));
}
__device__ __forceinline__ void mma1688(float* d, u32 a0, u32 a1, u32 b0) {
    asm volatile("mma.sync.aligned.m16n8k8.row.col.f32.f16.f16.f32 "
                 "{%0,%1,%2,%3},{%4,%5},{%6},{%0,%1,%2,%3};"
                 : "+f"(d[0]), "+f"(d[1]), "+f"(d[2]), "+f"(d[3])
                 : "r"(a0), "r"(a1), "r"(b0));
}
__device__ __forceinline__ u32 packh2(float x, float y) {
    __half2 h = __floats2half2_rn(x, y);
    return *(u32*)&h;
}

struct SmemAttn {
    __half K[NH * RS];
    __half V[NH * RS];
    __half Q[16 * RS];
    float  red1[8][16];
    float  red2[8][16];
    float  invr[16];
    float  os[8][16][16];
    int    rowmap[NH];
    unsigned char colcode[NH];
};

// ---------------------------------------------------------------------------
// Tiled neighborhood attention: block = (2x8 position tile) x (1 head).
// Masked-dense S[16 x 576] = Q*K^T on tensor cores, softmax, O = P*V.
// Halo addressing amortized per-row via smem rowmap; 16B vectorized copy.
// ---------------------------------------------------------------------------
__global__ __launch_bounds__(256) void attn_mma(void)
{
    extern __shared__ char smraw[];
    SmemAttn* sm = (SmemAttn*)smraw;

    const int tid  = threadIdx.x;
    const int warp = tid >> 5;
    const int lane = tid & 31;

    const int head = blockIdx.x & 7;
    const int tile = blockIdx.x >> 3;
    const int tw   = tile % 6;
    const int th   = (tile / 6) % 12;
    const int d0   = tile / 72;
    const int hy0  = th * 2;
    const int wx0  = tw * 8;

    // ---- phase 0: Q tile + rowmap + colcode ----
    {   // Q tile: 16 pos x 16 dims (256 threads exactly)
        int r = tid >> 4, k = tid & 15;
        int gp = ((d0 * HH + hy0 + (r >> 3)) * WWID + wx0 + (r & 7));
        sm->Q[r * RS + k] = g_qh[(size_t)gp * DIMC + head * HD + k];
    }
#pragma unroll
    for (int t = 0; t < 3; t++) {
        int rr = tid + t * 256;
        if (rr < NH) {
            int code = 0xFF, map = -1;
            if (rr < NREAL) {
                int d   = rr / 112;
                int rem = rr % 112;
                int ih  = rem / 14;
                int iw  = rem % 14;
                code = (ih << 4) | iw;
                int h2 = (hy0 + ih + 21) % HH;
                int w2 = (wx0 + iw + 45) % WWID;
                map = (d * HH + h2) * WWID + w2;
            }
            sm->colcode[rr] = (unsigned char)code;
            sm->rowmap[rr]  = map;
        }
    }
    __syncthreads();

    // ---- phase 1: halo K/V copy, 16B vectorized: 576 rows x {K lo, K hi, V lo, V hi}
    const __half* __restrict__ kh = g_kh;
    const __half* __restrict__ vh = g_vh;
#pragma unroll
    for (int t = 0; t < 9; t++) {
        int e   = tid + t * 256;      // 0..2303
        int row = e >> 2;
        int sel = e & 3;
        int c   = sel & 1;            // which 16B half of the 32B head-row
        int isv = sel >> 1;           // 0 = K, 1 = V
        int g   = sm->rowmap[row];
        uint4 val = make_uint4(0u, 0u, 0u, 0u);
        if (g >= 0) {
            const __half* src = (isv ? vh : kh) + (size_t)g * DIMC + head * HD + c * 8;
            val = *(const uint4*)src;
        }
        __half* dst = (isv ? sm->V : sm->K) + row * RS + c * 8;
        *(uint4*)dst = val;
    }
    __syncthreads();

    // ---- scores: S[16 x 72] per warp ----
    const u32 qb = smaddr(sm->Q);
    const u32 kb = smaddr(sm->K);
    const u32 vb = smaddr(sm->V);
    const int nb = warp * 72;

    u32 qa0, qa1, qa2, qa3;
    {
        int l4 = lane & 15, cg = lane >> 4;
        ldsm_x4(qa0, qa1, qa2, qa3, qb + (u32)(l4 * RS + cg * 8) * 2);
    }

    float c[9][4];
#pragma unroll
    for (int t = 0; t < 9; t++) { c[t][0] = c[t][1] = c[t][2] = c[t][3] = 0.f; }

#pragma unroll
    for (int t = 0; t < 9; t++) {
        int l4 = lane & 15;
        u32 addr = kb + (u32)((nb + t * 8 + (l4 & 7)) * RS + (l4 >> 3) * 8) * 2;
        u32 b0, b1;
        ldsm_x2(b0, b1, addr);
        mma16816(c[t], qa0, qa1, qa2, qa3, b0, b1);
    }

    // ---- mask + row max ----
    const int r0 = lane >> 2;
    const int r1 = r0 + 8;
    const int j  = r0;
    float mx0 = -1e30f, mx1 = -1e30f;
#pragma unroll
    for (int t = 0; t < 9; t++) {
        int cA = nb + t * 8 + 2 * (lane & 3);
        unsigned codeA = sm->colcode[cA];
        unsigned codeB = sm->colcode[cA + 1];
        int hA = codeA >> 4, wA = codeA & 15;
        int hB = codeB >> 4, wB = codeB & 15;
        bool vwA = (wA >= j) && (wA <= j + 6);
        bool vwB = (wB >= j) && (wB <= j + 6);
        if (!(vwA && hA <= 6)) c[t][0] = -1e30f;
        if (!(vwB && hB <= 6)) c[t][1] = -1e30f;
        if (!(vwA && hA >= 1)) c[t][2] = -1e30f;
        if (!(vwB && hB >= 1)) c[t][3] = -1e30f;
        mx0 = fmaxf(mx0, fmaxf(c[t][0], c[t][1]));
        mx1 = fmaxf(mx1, fmaxf(c[t][2], c[t][3]));
    }
    mx0 = fmaxf(mx0, __shfl_xor_sync(0xFFFFFFFF, mx0, 1));
    mx0 = fmaxf(mx0, __shfl_xor_sync(0xFFFFFFFF, mx0, 2));
    mx1 = fmaxf(mx1, __shfl_xor_sync(0xFFFFFFFF, mx1, 1));
    mx1 = fmaxf(mx1, __shfl_xor_sync(0xFFFFFFFF, mx1, 2));
    if ((lane & 3) == 0) { sm->red1[warp][r0] = mx0; sm->red1[warp][r1] = mx1; }
    __syncthreads();

    float M0 = sm->red1[0][r0], M1 = sm->red1[0][r1];
#pragma unroll
    for (int w = 1; w < 8; w++) {
        M0 = fmaxf(M0, sm->red1[w][r0]);
        M1 = fmaxf(M1, sm->red1[w][r1]);
    }

    // ---- exp + row sum ----
    float s0 = 0.f, s1 = 0.f;
#pragma unroll
    for (int t = 0; t < 9; t++) {
        c[t][0] = __expf(c[t][0] - M0); s0 += c[t][0];
        c[t][1] = __expf(c[t][1] - M0); s0 += c[t][1];
        c[t][2] = __expf(c[t][2] - M1); s1 += c[t][2];
        c[t][3] = __expf(c[t][3] - M1); s1 += c[t][3];
    }
    s0 += __shfl_xor_sync(0xFFFFFFFF, s0, 1);
    s0 += __shfl_xor_sync(0xFFFFFFFF, s0, 2);
    s1 += __shfl_xor_sync(0xFFFFFFFF, s1, 1);
    s1 += __shfl_xor_sync(0xFFFFFFFF, s1, 2);
    if ((lane & 3) == 0) { sm->red2[warp][r0] = s0; sm->red2[warp][r1] = s1; }
    __syncthreads();

    if (warp == 0 && (lane & 3) == 0) {
        float S0 = 0.f, S1 = 0.f;
#pragma unroll
        for (int w = 0; w < 8; w++) { S0 += sm->red2[w][r0]; S1 += sm->red2[w][r1]; }
        sm->invr[r0] = 1.f / S0;
        sm->invr[r1] = 1.f / S1;
    }

    // ---- O_partial = P @ V ----
    float dacc[8];
#pragma unroll
    for (int i = 0; i < 8; i++) dacc[i] = 0.f;

#pragma unroll
    for (int kc = 0; kc < 4; kc++) {
        u32 a0 = packh2(c[2 * kc][0], c[2 * kc][1]);
        u32 a1 = packh2(c[2 * kc][2], c[2 * kc][3]);
        u32 a2 = packh2(c[2 * kc + 1][0], c[2 * kc + 1][1]);
        u32 a3 = packh2(c[2 * kc + 1][2], c[2 * kc + 1][3]);
        int g = lane >> 3, rr = lane & 7;
        int row = nb + kc * 16 + ((g & 1) << 3) + rr;
        u32 addr = vb + (u32)(row * RS + (g >> 1) * 8) * 2;
        u32 b0, b1, b2, b3;
        ldsm_x4_t(b0, b1, b2, b3, addr);
        mma16816(dacc,     a0, a1, a2, a3, b0, b1);
        mma16816(dacc + 4, a0, a1, a2, a3, b2, b3);
    }
    {   // tail: cols 64..71
        u32 a0 = packh2(c[8][0], c[8][1]);
        u32 a1 = packh2(c[8][2], c[8][3]);
        int l4 = lane & 15;
        int row = nb + 64 + (l4 & 7);
        u32 addr = vb + (u32)(row * RS + (l4 >> 3) * 8) * 2;
        u32 b0, b1;
        ldsm_x2_t(b0, b1, addr);
        mma1688(dacc,     a0, a1, b0);
        mma1688(dacc + 4, a0, a1, b1);
    }

    // ---- stage partial outputs, reduce across warps ----
    {
        int q4 = lane & 3;
        sm->os[warp][r0][2 * q4 + 0] = dacc[0];
        sm->os[warp][r0][2 * q4 + 1] = dacc[1];
        sm->os[warp][r1][2 * q4 + 0] = dacc[2];
        sm->os[warp][r1][2 * q4 + 1] = dacc[3];
        sm->os[warp][r0][8 + 2 * q4 + 0] = dacc[4];
        sm->os[warp][r0][8 + 2 * q4 + 1] = dacc[5];
        sm->os[warp][r1][8 + 2 * q4 + 0] = dacc[6];
        sm->os[warp][r1][8 + 2 * q4 + 1] = dacc[7];
    }
    __syncthreads();

    {
        int r = tid >> 4, k = tid & 15;
        float s = 0.f;
#pragma unroll
        for (int w = 0; w < 8; w++) s += sm->os[w][r][k];
        s *= sm->invr[r];
        int gp = ((d0 * HH + hy0 + (r >> 3)) * WWID + wx0 + (r & 7));
        g_att[(size_t)gp * DIMC + head * HD + k] = s;
    }
}

// ---------------------------------------------------------------------------
extern "C" void kernel_launch(void* const* d_in, const int* in_sizes, int n_in,
                              void* d_out, int out_size)
{
    const float* x      = (const float*)d_in[0];
    const float* qkv_w  = (const float*)d_in[1];
    const float* qkv_b  = (const float*)d_in[2];
    const float* proj_w = (const float*)d_in[3];
    const float* proj_b = (const float*)d_in[4];
    float* out = (float*)d_out;

    float* att;
    cudaGetSymbolAddress((void**)&att, g_att);

    static int smem_set = 0;
    if (!smem_set) {
        cudaFuncSetAttribute(attn_mma, cudaFuncAttributeMaxDynamicSharedMemorySize,
                             (int)sizeof(SmemAttn));
        smem_set = 1;
    }

    gemm_qkv_h<<<dim3(NP / 64, 384 / 64), 256>>>(x, qkv_w, qkv_b);
    attn_mma<<<(NP / 16) * HEADS, 256, sizeof(SmemAttn)>>>();
    gemm_k128<<<dim3(NP / 64, 128 / 64), 256>>>(att, proj_w, proj_b, out, 128);
}